// round 11
// baseline (speedup 1.0000x reference)
#include <cuda_runtime.h>
#include <cuda_fp16.h>
#include <cstdint>

#define B_ 4
#define N_ 4096
#define C_ 1024
#define H_ 16
#define D_ 64
#define M_TOT (B_*N_)    // 16384
#define QKV_N (3*C_)     // 3072
#define NCHUNK 16
#define CHUNKN (N_/NCHUNK)   // 256

// ---------------- scratch (device globals; no runtime alloc) ----------------
__device__ float  g_qkv[(size_t)M_TOT * QKV_N];          // 201 MB
__device__ float  g_ctx[(size_t)B_ * H_ * D_ * D_];      // 1 MB
__device__ float  g_ctxp[NCHUNK][(size_t)B_ * H_ * D_ * D_]; // 16 MB
__device__ float  g_ctxs[NCHUNK][(size_t)B_ * H_ * D_];  // 256 KB
__device__ __half g_abuf[(size_t)M_TOT * C_];            // 32 MB (x-half, then q_sm-half)
__device__ __half g_wqkvT[(size_t)QKV_N * C_];           // 6 MB
__device__ __half g_wprojT[(size_t)C_ * C_];             // 2 MB
__device__ __half g_m2t[(size_t)B_ * C_ * C_];           // 8 MB  M2t[b][c, h*64+d]

__device__ __forceinline__ uint32_t smem_u32(const void* p) {
    uint32_t a;
    asm("{ .reg .u64 t; cvta.to.shared.u64 t, %1; cvt.u32.u64 %0, t; }" : "=r"(a) : "l"(p));
    return a;
}

#define CP_ASYNC16(saddr, gptr) \
    asm volatile("cp.async.cg.shared.global [%0], [%1], 16;" :: "r"(saddr), "l"(gptr))
#define CP_COMMIT() asm volatile("cp.async.commit_group;" ::: "memory")
#define CP_WAIT2()  asm volatile("cp.async.wait_group 2;" ::: "memory")

#define LDMATRIX_X4(r0, r1, r2, r3, addr) \
    asm volatile("ldmatrix.sync.aligned.m8n8.x4.shared.b16 {%0, %1, %2, %3}, [%4];" \
        : "=r"(r0), "=r"(r1), "=r"(r2), "=r"(r3) : "r"(addr))

__device__ __forceinline__ void mma_16x8x16(
    float* c, uint32_t a0, uint32_t a1, uint32_t a2, uint32_t a3,
    uint32_t b0, uint32_t b1)
{
    asm volatile(
        "mma.sync.aligned.m16n8k16.row.col.f32.f16.f16.f32 "
        "{%0, %1, %2, %3}, {%4, %5, %6, %7}, {%8, %9}, {%0, %1, %2, %3};"
        : "+f"(c[0]), "+f"(c[1]), "+f"(c[2]), "+f"(c[3])
        : "r"(a0), "r"(a1), "r"(a2), "r"(a3), "r"(b0), "r"(b1));
}

// ---------------------------------------------------------------------------
// fp16 warp-MMA GEMM (batched): C[z][M,N] = A[z][M,K] @ Bt[z][N,K]^T + bias
// BM=128, BN=128, BK=32 halves, 4-stage cp.async, ldmatrix, 4 warps 64x64.
// ---------------------------------------------------------------------------
#define ROWB 80
#define STAGE_OP_BYTES (128 * ROWB)
#define STAGE_BYTES  (2 * STAGE_OP_BYTES)
#define GEMM_SMEM    (4 * STAGE_BYTES)

__global__ __launch_bounds__(128, 2) void gemm_mma_fp16(
    const __half* __restrict__ A, const __half* __restrict__ Bt,
    const float* __restrict__ bias, float* __restrict__ Cm,
    int M, int N, int K,
    size_t aBatch, size_t bBatch, size_t cBatch)
{
    extern __shared__ char smem[];
    const uint32_t smem_base = smem_u32(smem);

    const int tid = threadIdx.x;
    const int lane = tid & 31;
    const int wid = tid >> 5;
    const int wm = (wid >> 1) * 64;
    const int wn = (wid & 1) * 64;
    const int m0 = blockIdx.y * 128, n0 = blockIdx.x * 128;
    const int z = blockIdx.z;

    const __half* Ag = A + z * aBatch + (size_t)m0 * K;
    const __half* Bg = Bt + z * bBatch + (size_t)n0 * K;
    float* Cz = Cm + z * cBatch;

    const int r0 = tid >> 2;
    const int kb = (tid & 3) * 16;
    const int kf = (tid & 3) * 8;

    const int g = lane >> 2;
    const int t4 = lane & 3;

    uint32_t a_off[4];
    #pragma unroll
    for (int mt = 0; mt < 4; mt++)
        a_off[mt] = (uint32_t)((wm + mt * 16 + (lane & 15)) * ROWB + ((lane >> 4) << 4));
    uint32_t b_off[4];
    #pragma unroll
    for (int p = 0; p < 4; p++)
        b_off[p] = (uint32_t)((wn + p * 16 + ((lane >> 4) << 3) + (lane & 7)) * ROWB
                              + (((lane >> 3) & 1) << 4) + STAGE_OP_BYTES);

    float acc[4][8][4];
    #pragma unroll
    for (int i = 0; i < 4; i++)
        #pragma unroll
        for (int j = 0; j < 8; j++)
            #pragma unroll
            for (int q = 0; q < 4; q++) acc[i][j][q] = 0.f;

    const int iters = K >> 5;

    #pragma unroll
    for (int s = 0; s < 3; s++) {
        const uint32_t sa = smem_base + s * STAGE_BYTES;
        const uint32_t sb = sa + STAGE_OP_BYTES;
        const __half* Asrc = Ag + s * 32;
        const __half* Bsrc = Bg + s * 32;
        #pragma unroll
        for (int rr = 0; rr < 4; rr++) {
            const int row = r0 + rr * 32;
            CP_ASYNC16(sa + row * ROWB + kb, Asrc + (size_t)row * K + kf);
            CP_ASYNC16(sb + row * ROWB + kb, Bsrc + (size_t)row * K + kf);
        }
        CP_COMMIT();
    }

    for (int it = 0; it < iters; it++) {
        CP_WAIT2();
        __syncthreads();

        if (it + 3 < iters) {
            const int s = (it + 3) & 3;
            const uint32_t sa = smem_base + s * STAGE_BYTES;
            const uint32_t sb = sa + STAGE_OP_BYTES;
            const __half* Asrc = Ag + (it + 3) * 32;
            const __half* Bsrc = Bg + (it + 3) * 32;
            #pragma unroll
            for (int rr = 0; rr < 4; rr++) {
                const int row = r0 + rr * 32;
                CP_ASYNC16(sa + row * ROWB + kb, Asrc + (size_t)row * K + kf);
                CP_ASYNC16(sb + row * ROWB + kb, Bsrc + (size_t)row * K + kf);
            }
        }
        CP_COMMIT();

        const uint32_t stage = smem_base + (it & 3) * STAGE_BYTES;

        #pragma unroll
        for (int s = 0; s < 2; s++) {
            const uint32_t ksb = (uint32_t)(s * 32);
            uint32_t afr[4][4];
            #pragma unroll
            for (int mt = 0; mt < 4; mt++)
                LDMATRIX_X4(afr[mt][0], afr[mt][1], afr[mt][2], afr[mt][3],
                            stage + a_off[mt] + ksb);
            uint32_t bfr[4][4];
            #pragma unroll
            for (int p = 0; p < 4; p++)
                LDMATRIX_X4(bfr[p][0], bfr[p][1], bfr[p][2], bfr[p][3],
                            stage + b_off[p] + ksb);
            #pragma unroll
            for (int nt = 0; nt < 8; nt++) {
                uint32_t b0 = bfr[nt >> 1][(nt & 1) * 2];
                uint32_t b1 = bfr[nt >> 1][(nt & 1) * 2 + 1];
                #pragma unroll
                for (int mt = 0; mt < 4; mt++)
                    mma_16x8x16(acc[mt][nt], afr[mt][0], afr[mt][1], afr[mt][2], afr[mt][3], b0, b1);
            }
        }
    }

    #pragma unroll
    for (int mt = 0; mt < 4; mt++) {
        #pragma unroll
        for (int nt = 0; nt < 8; nt++) {
            int row = m0 + wm + mt * 16 + g;
            int col = n0 + wn + nt * 8 + t4 * 2;
            float bx = bias[col], by = bias[col + 1];
            float2 o0 = {acc[mt][nt][0] + bx, acc[mt][nt][1] + by};
            float2 o1 = {acc[mt][nt][2] + bx, acc[mt][nt][3] + by};
            *(float2*)&Cz[(size_t)row * N + col] = o0;
            *(float2*)&Cz[(size_t)(row + 8) * N + col] = o1;
        }
    }
}

// ---------------------------------------------------------------------------
// W [K,N] fp32 -> Wt [N,K] fp16 transpose
// ---------------------------------------------------------------------------
__global__ void transpose_kernel(const float* __restrict__ W, __half* __restrict__ Wt,
                                 int K, int N)
{
    __shared__ float t[32][33];
    int n0 = blockIdx.x * 32, k0 = blockIdx.y * 32;
    for (int i = threadIdx.y; i < 32; i += 8)
        t[i][threadIdx.x] = W[(size_t)(k0 + i) * N + n0 + threadIdx.x];
    __syncthreads();
    for (int i = threadIdx.y; i < 32; i += 8)
        Wt[(size_t)(n0 + i) * K + k0 + threadIdx.x] = __float2half_rn(t[threadIdx.x][i]);
}

// round x -> fp16
__global__ __launch_bounds__(256) void round_x_kernel(
    const float* __restrict__ x, __half* __restrict__ xh)
{
    size_t i = ((size_t)blockIdx.x * 256 + threadIdx.x) * 4;
    float4 v = *(const float4*)(x + i);
    __half2 h0 = __floats2half2_rn(v.x, v.y);
    __half2 h1 = __floats2half2_rn(v.z, v.w);
    uint2 o = {*(uint32_t*)&h0, *(uint32_t*)&h1};
    *(uint2*)(xh + i) = o;
}

// ---------------------------------------------------------------------------
// ctx partial (fused k-softmax): exp(k)^T v partials + exp-colsum partials.
// ---------------------------------------------------------------------------
__global__ __launch_bounds__(256) void ctx_partial_kernel(
    const float* __restrict__ qkv, float* __restrict__ ctxp, float* __restrict__ ctxs)
{
    int bh = blockIdx.x;
    int chunk = blockIdx.y;
    int b = bh >> 4, h = bh & 15;
    const float* kbase = qkv + (size_t)b * N_ * QKV_N + C_     + h * D_;
    const float* vbase = qkv + (size_t)b * N_ * QKV_N + 2 * C_ + h * D_;

    __shared__ float Ks[32][64];
    __shared__ float Vs[32][64];

    int tid = threadIdx.x;
    int tx = tid & 15, ty = tid >> 4;
    int ln = tid >> 3;
    int ld = (tid & 7) * 8;

    float acc[4][4];
    float accs[4];
    #pragma unroll
    for (int i = 0; i < 4; i++) {
        accs[i] = 0.f;
        #pragma unroll
        for (int j = 0; j < 4; j++) acc[i][j] = 0.f;
    }

    int nbeg = chunk * CHUNKN, nend = nbeg + CHUNKN;
    for (int nt = nbeg; nt < nend; nt += 32) {
        const float* kp = kbase + (size_t)(nt + ln) * QKV_N + ld;
        const float* vp = vbase + (size_t)(nt + ln) * QKV_N + ld;
        float4 k0 = *(const float4*)kp;
        float4 k1 = *(const float4*)(kp + 4);
        float4 v0 = *(const float4*)vp;
        float4 v1 = *(const float4*)(vp + 4);
        k0.x = __expf(k0.x); k0.y = __expf(k0.y); k0.z = __expf(k0.z); k0.w = __expf(k0.w);
        k1.x = __expf(k1.x); k1.y = __expf(k1.y); k1.z = __expf(k1.z); k1.w = __expf(k1.w);
        __syncthreads();
        *(float4*)&Ks[ln][ld]     = k0;
        *(float4*)&Ks[ln][ld + 4] = k1;
        *(float4*)&Vs[ln][ld]     = v0;
        *(float4*)&Vs[ln][ld + 4] = v1;
        __syncthreads();

        #pragma unroll 8
        for (int n = 0; n < 32; n++) {
            float4 a = *(float4*)&Ks[n][ty * 4];
            float4 v = *(float4*)&Vs[n][tx * 4];
            float av[4] = {a.x, a.y, a.z, a.w};
            float bv[4] = {v.x, v.y, v.z, v.w};
            #pragma unroll
            for (int i = 0; i < 4; i++) {
                accs[i] += av[i];
                #pragma unroll
                for (int j = 0; j < 4; j++)
                    acc[i][j] = fmaf(av[i], bv[j], acc[i][j]);
            }
        }
    }

    float* cp = ctxp + ((size_t)chunk * (B_ * H_) + bh) * D_ * D_;
    #pragma unroll
    for (int i = 0; i < 4; i++) {
        float4 o = {acc[i][0], acc[i][1], acc[i][2], acc[i][3]};
        *(float4*)&cp[(ty * 4 + i) * D_ + tx * 4] = o;
    }
    if (tx == 0) {
        float* sp = ctxs + (size_t)chunk * (B_ * H_ * D_) + bh * D_;
        #pragma unroll
        for (int i = 0; i < 4; i++)
            sp[ty * 4 + i] = accs[i];
    }
}

__global__ __launch_bounds__(256) void ctx_reduce_kernel(
    const float* __restrict__ ctxp, const float* __restrict__ ctxs,
    float* __restrict__ ctx)
{
    int idx = blockIdx.x * 256 + threadIdx.x;
    const int total = B_ * H_ * D_ * D_;
    if (idx >= total) return;
    int bh = idx >> 12;
    int d  = (idx >> 6) & 63;
    float s = 0.f, se = 0.f;
    #pragma unroll
    for (int c = 0; c < NCHUNK; c++) {
        s  += ctxp[(size_t)c * total + idx];
        se += ctxs[(size_t)c * (B_ * H_ * D_) + bh * D_ + d];
    }
    ctx[idx] = s / se;
}

// ---------------------------------------------------------------------------
// q softmax -> fp16. One warp per (b,n) row; lane pair per head.
// qsm[row, h*64+d] = softmax_d(q[row, h, :])
// ---------------------------------------------------------------------------
__global__ __launch_bounds__(256) void qsm_prep_kernel(
    const float* __restrict__ qkv, __half* __restrict__ qsm)
{
    int row = blockIdx.x * 8 + (threadIdx.x >> 5);
    int lane = threadIdx.x & 31;
    int h = lane >> 1, hf = lane & 1;
    const float* p = qkv + (size_t)row * QKV_N + h * 64 + hf * 32;

    float v[32];
    #pragma unroll
    for (int j = 0; j < 8; j++) {
        float4 t = *(const float4*)(p + j * 4);
        v[4*j] = t.x; v[4*j+1] = t.y; v[4*j+2] = t.z; v[4*j+3] = t.w;
    }
    float m = v[0];
    #pragma unroll
    for (int j = 1; j < 32; j++) m = fmaxf(m, v[j]);
    m = fmaxf(m, __shfl_xor_sync(0xffffffffu, m, 1));
    float s = 0.f;
    #pragma unroll
    for (int j = 0; j < 32; j++) { v[j] = __expf(v[j] - m); s += v[j]; }
    s += __shfl_xor_sync(0xffffffffu, s, 1);
    float inv = 1.f / s;

    uint32_t pk[16];
    #pragma unroll
    for (int j = 0; j < 16; j++) {
        __half2 hh = __floats2half2_rn(v[2*j] * inv, v[2*j+1] * inv);
        pk[j] = *(uint32_t*)&hh;
    }
    __half* op = qsm + (size_t)row * C_ + h * 64 + hf * 32;
    #pragma unroll
    for (int j = 0; j < 4; j++) {
        uint4 o = {pk[4*j], pk[4*j+1], pk[4*j+2], pk[4*j+3]};
        *(uint4*)(op + j * 8) = o;
    }
}

// ---------------------------------------------------------------------------
// M2t[b][c, h*64+d] = sum_e ctx[b,h,d,e] * wprojT[c, h*64+e]   (fp16 out)
// grid (8 c-chunks, H, B), 256 threads.
// ---------------------------------------------------------------------------
__global__ __launch_bounds__(256) void m2_kernel(
    const float* __restrict__ ctx, const __half* __restrict__ wprojT,
    __half* __restrict__ m2t)
{
    int b = blockIdx.z, h = blockIdx.y, cc = blockIdx.x;
    __shared__ float cs[64 * 64];

    const float* cp = ctx + (size_t)(b * H_ + h) * D_ * D_;
    for (int i = threadIdx.x * 4; i < 4096; i += 1024)
        *(float4*)&cs[i] = *(const float4*)&cp[i];
    __syncthreads();

    int c = cc * 128 + (threadIdx.x >> 1);
    int d0 = (threadIdx.x & 1) * 32;

    float w[64];
    const __half2* wp = (const __half2*)(wprojT + (size_t)c * C_ + h * 64);
    #pragma unroll
    for (int e = 0; e < 32; e++) {
        float2 f = __half22float2(wp[e]);
        w[2*e] = f.x; w[2*e+1] = f.y;
    }

    float acc[32];
    #pragma unroll
    for (int i = 0; i < 32; i++) {
        const float4* rowp = (const float4*)(cs + (d0 + i) * 64);
        float a = 0.f;
        #pragma unroll
        for (int e4 = 0; e4 < 16; e4++) {
            float4 c4 = rowp[e4];
            a = fmaf(c4.x, w[4*e4], a);
            a = fmaf(c4.y, w[4*e4+1], a);
            a = fmaf(c4.z, w[4*e4+2], a);
            a = fmaf(c4.w, w[4*e4+3], a);
        }
        acc[i] = a;
    }

    uint32_t pk[16];
    #pragma unroll
    for (int j = 0; j < 16; j++) {
        __half2 hh = __floats2half2_rn(acc[2*j], acc[2*j+1]);
        pk[j] = *(uint32_t*)&hh;
    }
    __half* op = m2t + (size_t)b * C_ * C_ + (size_t)c * C_ + h * 64 + d0;
    #pragma unroll
    for (int j = 0; j < 4; j++) {
        uint4 o = {pk[4*j], pk[4*j+1], pk[4*j+2], pk[4*j+3]};
        *(uint4*)(op + j * 8) = o;
    }
}

// ---------------------------------------------------------------------------
extern "C" void kernel_launch(void* const* d_in, const int* in_sizes, int n_in,
                              void* d_out, int out_size)
{
    (void)in_sizes; (void)n_in; (void)out_size;
    const float* x     = (const float*)d_in[0];
    const float* Wqkv  = (const float*)d_in[1];
    const float* bqkv  = (const float*)d_in[2];
    const float* Wproj = (const float*)d_in[3];
    const float* bproj = (const float*)d_in[4];
    float* out = (float*)d_out;

    float *qkv, *ctx, *ctxp, *ctxs;
    __half *abuf, *wqkvT, *wprojT, *m2t;
    cudaGetSymbolAddress((void**)&qkv,    g_qkv);
    cudaGetSymbolAddress((void**)&ctx,    g_ctx);
    cudaGetSymbolAddress((void**)&ctxp,   g_ctxp);
    cudaGetSymbolAddress((void**)&ctxs,   g_ctxs);
    cudaGetSymbolAddress((void**)&abuf,   g_abuf);
    cudaGetSymbolAddress((void**)&wqkvT,  g_wqkvT);
    cudaGetSymbolAddress((void**)&wprojT, g_wprojT);
    cudaGetSymbolAddress((void**)&m2t,    g_m2t);

    cudaFuncSetAttribute(gemm_mma_fp16,
                         cudaFuncAttributeMaxDynamicSharedMemorySize, GEMM_SMEM);

    // 0) x -> fp16; weights -> [N,K] fp16
    round_x_kernel<<<M_TOT * C_ / 1024, 256>>>(x, abuf);
    transpose_kernel<<<dim3(QKV_N / 32, C_ / 32), dim3(32, 8)>>>(Wqkv, wqkvT, C_, QKV_N);
    transpose_kernel<<<dim3(C_ / 32, C_ / 32), dim3(32, 8)>>>(Wproj, wprojT, C_, C_);

    // 1) qkv = x @ W_qkv + b_qkv
    gemm_mma_fp16<<<dim3(QKV_N / 128, M_TOT / 128, 1), 128, GEMM_SMEM>>>(
        abuf, wqkvT, bqkv, qkv, M_TOT, QKV_N, C_, 0, 0, 0);

    // 2) context = softmax_N(k)^T v  (fused exp + colsum, deterministic reduce)
    ctx_partial_kernel<<<dim3(B_ * H_, NCHUNK), 256>>>(qkv, ctxp, ctxs);
    ctx_reduce_kernel<<<(B_ * H_ * D_ * D_ + 255) / 256, 256>>>(ctxp, ctxs, ctx);

    // 3) q_sm fp16 (overwrites x-half); M2t[b] = (ctx @ Wproj_head)^T fp16
    qsm_prep_kernel<<<M_TOT / 8, 256>>>(qkv, abuf);
    m2_kernel<<<dim3(8, H_, B_), 256>>>(ctx, wprojT, m2t);

    // 4) out[b] = q_sm[b] @ M2t[b]^T + bproj   (batched fp16 MMA GEMM)
    gemm_mma_fp16<<<dim3(C_ / 128, N_ / 128, B_), 128, GEMM_SMEM>>>(
        abuf, m2t, bproj, out, N_, C_, C_,
        (size_t)N_ * C_, (size_t)C_ * C_, (size_t)N_ * C_);
}

// round 14
// speedup vs baseline: 1.0307x; 1.0307x over previous
#include <cuda_runtime.h>
#include <cuda_fp16.h>
#include <cstdint>

#define B_ 4
#define N_ 4096
#define C_ 1024
#define H_ 16
#define D_ 64
#define M_TOT (B_*N_)    // 16384
#define QKV_N (3*C_)     // 3072
#define NCHUNK 16
#define CHUNKN (N_/NCHUNK)   // 256

// ---------------- scratch (device globals; no runtime alloc) ----------------
__device__ float  g_qkv[(size_t)M_TOT * QKV_N];          // 201 MB (k,v regions used)
__device__ float  g_ctx[(size_t)B_ * H_ * D_ * D_];      // 1 MB
__device__ float  g_ctxp[NCHUNK][(size_t)B_ * H_ * D_ * D_]; // 16 MB
__device__ float  g_ctxs[NCHUNK][(size_t)B_ * H_ * D_];  // 256 KB
__device__ __half g_abuf[(size_t)M_TOT * C_];            // 32 MB (x as fp16)
__device__ __half g_qsm[(size_t)M_TOT * C_];             // 32 MB (softmaxed q, fp16)
__device__ __half g_wqkvT[(size_t)QKV_N * C_];           // 6 MB
__device__ __half g_wprojT[(size_t)C_ * C_];             // 2 MB
__device__ __half g_m2t[(size_t)B_ * C_ * C_];           // 8 MB

__device__ __forceinline__ uint32_t smem_u32(const void* p) {
    uint32_t a;
    asm("{ .reg .u64 t; cvta.to.shared.u64 t, %1; cvt.u32.u64 %0, t; }" : "=r"(a) : "l"(p));
    return a;
}

#define CP_ASYNC16(saddr, gptr) \
    asm volatile("cp.async.cg.shared.global [%0], [%1], 16;" :: "r"(saddr), "l"(gptr))
#define CP_COMMIT() asm volatile("cp.async.commit_group;" ::: "memory")
#define CP_WAIT2()  asm volatile("cp.async.wait_group 2;" ::: "memory")

#define LDMATRIX_X4(r0, r1, r2, r3, addr) \
    asm volatile("ldmatrix.sync.aligned.m8n8.x4.shared.b16 {%0, %1, %2, %3}, [%4];" \
        : "=r"(r0), "=r"(r1), "=r"(r2), "=r"(r3) : "r"(addr))

__device__ __forceinline__ void mma_16x8x16(
    float* c, uint32_t a0, uint32_t a1, uint32_t a2, uint32_t a3,
    uint32_t b0, uint32_t b1)
{
    asm volatile(
        "mma.sync.aligned.m16n8k16.row.col.f32.f16.f16.f32 "
        "{%0, %1, %2, %3}, {%4, %5, %6, %7}, {%8, %9}, {%0, %1, %2, %3};"
        : "+f"(c[0]), "+f"(c[1]), "+f"(c[2]), "+f"(c[3])
        : "r"(a0), "r"(a1), "r"(a2), "r"(a3), "r"(b0), "r"(b1));
}

// ---------------------------------------------------------------------------
// fp16 warp-MMA GEMM (batched, templated epilogue):
//   MODE 0: C = A @ Bt^T + bias (fp32 out)
//   MODE 1: qkv GEMM. q cols [0,C): fused softmax-over-head -> fp16 qsm.
//           k cols [C,2C): exp(val+bias) -> fp32 qkv. v: plain fp32 qkv.
// BM=128, BN=128, BK=32 halves, 4-stage cp.async, ldmatrix, 4 warps 64x64.
// ---------------------------------------------------------------------------
#define ROWB 80
#define STAGE_OP_BYTES (128 * ROWB)
#define STAGE_BYTES  (2 * STAGE_OP_BYTES)
#define GEMM_SMEM    (4 * STAGE_BYTES)

template<int MODE>
__global__ __launch_bounds__(128, 2) void gemm_mma_fp16(
    const __half* __restrict__ A, const __half* __restrict__ Bt,
    const float* __restrict__ bias, float* __restrict__ Cm,
    __half* __restrict__ qsm,
    int M, int N, int K,
    size_t aBatch, size_t bBatch, size_t cBatch)
{
    extern __shared__ char smem[];
    const uint32_t smem_base = smem_u32(smem);

    const int tid = threadIdx.x;
    const int lane = tid & 31;
    const int wid = tid >> 5;
    const int wm = (wid >> 1) * 64;
    const int wn = (wid & 1) * 64;
    const int m0 = blockIdx.y * 128, n0 = blockIdx.x * 128;
    const int z = blockIdx.z;

    const __half* Ag = A + z * aBatch + (size_t)m0 * K;
    const __half* Bg = Bt + z * bBatch + (size_t)n0 * K;
    float* Cz = Cm + z * cBatch;

    const int r0 = tid >> 2;
    const int kb = (tid & 3) * 16;
    const int kf = (tid & 3) * 8;

    const int g = lane >> 2;
    const int t4 = lane & 3;

    uint32_t a_off[4];
    #pragma unroll
    for (int mt = 0; mt < 4; mt++)
        a_off[mt] = (uint32_t)((wm + mt * 16 + (lane & 15)) * ROWB + ((lane >> 4) << 4));
    uint32_t b_off[4];
    #pragma unroll
    for (int p = 0; p < 4; p++)
        b_off[p] = (uint32_t)((wn + p * 16 + ((lane >> 4) << 3) + (lane & 7)) * ROWB
                              + (((lane >> 3) & 1) << 4) + STAGE_OP_BYTES);

    float acc[4][8][4];
    #pragma unroll
    for (int i = 0; i < 4; i++)
        #pragma unroll
        for (int j = 0; j < 8; j++)
            #pragma unroll
            for (int q = 0; q < 4; q++) acc[i][j][q] = 0.f;

    const int iters = K >> 5;

    #pragma unroll
    for (int s = 0; s < 3; s++) {
        const uint32_t sa = smem_base + s * STAGE_BYTES;
        const uint32_t sb = sa + STAGE_OP_BYTES;
        const __half* Asrc = Ag + s * 32;
        const __half* Bsrc = Bg + s * 32;
        #pragma unroll
        for (int rr = 0; rr < 4; rr++) {
            const int row = r0 + rr * 32;
            CP_ASYNC16(sa + row * ROWB + kb, Asrc + (size_t)row * K + kf);
            CP_ASYNC16(sb + row * ROWB + kb, Bsrc + (size_t)row * K + kf);
        }
        CP_COMMIT();
    }

    for (int it = 0; it < iters; it++) {
        CP_WAIT2();
        __syncthreads();

        if (it + 3 < iters) {
            const int s = (it + 3) & 3;
            const uint32_t sa = smem_base + s * STAGE_BYTES;
            const uint32_t sb = sa + STAGE_OP_BYTES;
            const __half* Asrc = Ag + (it + 3) * 32;
            const __half* Bsrc = Bg + (it + 3) * 32;
            #pragma unroll
            for (int rr = 0; rr < 4; rr++) {
                const int row = r0 + rr * 32;
                CP_ASYNC16(sa + row * ROWB + kb, Asrc + (size_t)row * K + kf);
                CP_ASYNC16(sb + row * ROWB + kb, Bsrc + (size_t)row * K + kf);
            }
        }
        CP_COMMIT();

        const uint32_t stage = smem_base + (it & 3) * STAGE_BYTES;

        #pragma unroll
        for (int s = 0; s < 2; s++) {
            const uint32_t ksb = (uint32_t)(s * 32);
            uint32_t afr[4][4];
            #pragma unroll
            for (int mt = 0; mt < 4; mt++)
                LDMATRIX_X4(afr[mt][0], afr[mt][1], afr[mt][2], afr[mt][3],
                            stage + a_off[mt] + ksb);
            uint32_t bfr[4][4];
            #pragma unroll
            for (int p = 0; p < 4; p++)
                LDMATRIX_X4(bfr[p][0], bfr[p][1], bfr[p][2], bfr[p][3],
                            stage + b_off[p] + ksb);
            #pragma unroll
            for (int nt = 0; nt < 8; nt++) {
                uint32_t b0 = bfr[nt >> 1][(nt & 1) * 2];
                uint32_t b1 = bfr[nt >> 1][(nt & 1) * 2 + 1];
                #pragma unroll
                for (int mt = 0; mt < 4; mt++)
                    mma_16x8x16(acc[mt][nt], afr[mt][0], afr[mt][1], afr[mt][2], afr[mt][3], b0, b1);
            }
        }
    }

    // -------- epilogue --------
    if (MODE == 1 && n0 < C_) {
        // q region: fused softmax over head_dim -> fp16 qsm (dedicated buffer).
        // Each warp's 64-col tile == one head; a row's 64 vals live in a lane quad.
        float bxv[8], byv[8];
        #pragma unroll
        for (int nt = 0; nt < 8; nt++) {
            int col = n0 + wn + nt * 8 + t4 * 2;
            bxv[nt] = bias[col];
            byv[nt] = bias[col + 1];
        }
        #pragma unroll
        for (int mt = 0; mt < 4; mt++) {
            float vt[16], vb[16];
            #pragma unroll
            for (int nt = 0; nt < 8; nt++) {
                vt[2*nt]   = acc[mt][nt][0] + bxv[nt];
                vt[2*nt+1] = acc[mt][nt][1] + byv[nt];
                vb[2*nt]   = acc[mt][nt][2] + bxv[nt];
                vb[2*nt+1] = acc[mt][nt][3] + byv[nt];
            }
            float mtv = vt[0], mbv = vb[0];
            #pragma unroll
            for (int j = 1; j < 16; j++) { mtv = fmaxf(mtv, vt[j]); mbv = fmaxf(mbv, vb[j]); }
            mtv = fmaxf(mtv, __shfl_xor_sync(0xffffffffu, mtv, 1));
            mtv = fmaxf(mtv, __shfl_xor_sync(0xffffffffu, mtv, 2));
            mbv = fmaxf(mbv, __shfl_xor_sync(0xffffffffu, mbv, 1));
            mbv = fmaxf(mbv, __shfl_xor_sync(0xffffffffu, mbv, 2));
            float st = 0.f, sb = 0.f;
            #pragma unroll
            for (int j = 0; j < 16; j++) {
                vt[j] = __expf(vt[j] - mtv); st += vt[j];
                vb[j] = __expf(vb[j] - mbv); sb += vb[j];
            }
            st += __shfl_xor_sync(0xffffffffu, st, 1);
            st += __shfl_xor_sync(0xffffffffu, st, 2);
            sb += __shfl_xor_sync(0xffffffffu, sb, 1);
            sb += __shfl_xor_sync(0xffffffffu, sb, 2);
            float it_ = 1.f / st, ib_ = 1.f / sb;
            int row = m0 + wm + mt * 16 + g;
            #pragma unroll
            for (int nt = 0; nt < 8; nt++) {
                int col = n0 + wn + nt * 8 + t4 * 2;
                __half2 ht = __floats2half2_rn(vt[2*nt] * it_, vt[2*nt+1] * it_);
                __half2 hb = __floats2half2_rn(vb[2*nt] * ib_, vb[2*nt+1] * ib_);
                *(uint32_t*)&qsm[(size_t)row * C_ + col] = *(uint32_t*)&ht;
                *(uint32_t*)&qsm[(size_t)(row + 8) * C_ + col] = *(uint32_t*)&hb;
            }
        }
    } else {
        const bool isK = (MODE == 1) && (n0 < 2 * C_);
        #pragma unroll
        for (int mt = 0; mt < 4; mt++) {
            #pragma unroll
            for (int nt = 0; nt < 8; nt++) {
                int row = m0 + wm + mt * 16 + g;
                int col = n0 + wn + nt * 8 + t4 * 2;
                float bx = bias[col], by = bias[col + 1];
                float2 o0 = {acc[mt][nt][0] + bx, acc[mt][nt][1] + by};
                float2 o1 = {acc[mt][nt][2] + bx, acc[mt][nt][3] + by};
                if (isK) {
                    o0.x = __expf(o0.x); o0.y = __expf(o0.y);
                    o1.x = __expf(o1.x); o1.y = __expf(o1.y);
                }
                *(float2*)&Cz[(size_t)row * N + col] = o0;
                *(float2*)&Cz[(size_t)(row + 8) * N + col] = o1;
            }
        }
    }
}

// ---------------------------------------------------------------------------
// W [K,N] fp32 -> Wt [N,K] fp16 transpose
// ---------------------------------------------------------------------------
__global__ void transpose_kernel(const float* __restrict__ W, __half* __restrict__ Wt,
                                 int K, int N)
{
    __shared__ float t[32][33];
    int n0 = blockIdx.x * 32, k0 = blockIdx.y * 32;
    for (int i = threadIdx.y; i < 32; i += 8)
        t[i][threadIdx.x] = W[(size_t)(k0 + i) * N + n0 + threadIdx.x];
    __syncthreads();
    for (int i = threadIdx.y; i < 32; i += 8)
        Wt[(size_t)(n0 + i) * K + k0 + threadIdx.x] = __float2half_rn(t[threadIdx.x][i]);
}

// round x -> fp16
__global__ __launch_bounds__(256) void round_x_kernel(
    const float* __restrict__ x, __half* __restrict__ xh)
{
    size_t i = ((size_t)blockIdx.x * 256 + threadIdx.x) * 4;
    float4 v = *(const float4*)(x + i);
    __half2 h0 = __floats2half2_rn(v.x, v.y);
    __half2 h1 = __floats2half2_rn(v.z, v.w);
    uint2 o = {*(uint32_t*)&h0, *(uint32_t*)&h1};
    *(uint2*)(xh + i) = o;
}

// ---------------------------------------------------------------------------
// ctx partial: k region already holds exp(k). Accumulate ek^T v + colsums.
// ---------------------------------------------------------------------------
__global__ __launch_bounds__(256) void ctx_partial_kernel(
    const float* __restrict__ qkv, float* __restrict__ ctxp, float* __restrict__ ctxs)
{
    int bh = blockIdx.x;
    int chunk = blockIdx.y;
    int b = bh >> 4, h = bh & 15;
    const float* kbase = qkv + (size_t)b * N_ * QKV_N + C_     + h * D_;
    const float* vbase = qkv + (size_t)b * N_ * QKV_N + 2 * C_ + h * D_;

    __shared__ float Ks[32][64];
    __shared__ float Vs[32][64];

    int tid = threadIdx.x;
    int tx = tid & 15, ty = tid >> 4;
    int ln = tid >> 3;
    int ld = (tid & 7) * 8;

    float acc[4][4];
    float accs[4];
    #pragma unroll
    for (int i = 0; i < 4; i++) {
        accs[i] = 0.f;
        #pragma unroll
        for (int j = 0; j < 4; j++) acc[i][j] = 0.f;
    }

    int nbeg = chunk * CHUNKN, nend = nbeg + CHUNKN;
    for (int nt = nbeg; nt < nend; nt += 32) {
        const float* kp = kbase + (size_t)(nt + ln) * QKV_N + ld;
        const float* vp = vbase + (size_t)(nt + ln) * QKV_N + ld;
        float4 k0 = *(const float4*)kp;
        float4 k1 = *(const float4*)(kp + 4);
        float4 v0 = *(const float4*)vp;
        float4 v1 = *(const float4*)(vp + 4);
        __syncthreads();
        *(float4*)&Ks[ln][ld]     = k0;
        *(float4*)&Ks[ln][ld + 4] = k1;
        *(float4*)&Vs[ln][ld]     = v0;
        *(float4*)&Vs[ln][ld + 4] = v1;
        __syncthreads();

        #pragma unroll 8
        for (int n = 0; n < 32; n++) {
            float4 a = *(float4*)&Ks[n][ty * 4];
            float4 v = *(float4*)&Vs[n][tx * 4];
            float av[4] = {a.x, a.y, a.z, a.w};
            float bv[4] = {v.x, v.y, v.z, v.w};
            #pragma unroll
            for (int i = 0; i < 4; i++) {
                accs[i] += av[i];
                #pragma unroll
                for (int j = 0; j < 4; j++)
                    acc[i][j] = fmaf(av[i], bv[j], acc[i][j]);
            }
        }
    }

    float* cp = ctxp + ((size_t)chunk * (B_ * H_) + bh) * D_ * D_;
    #pragma unroll
    for (int i = 0; i < 4; i++) {
        float4 o = {acc[i][0], acc[i][1], acc[i][2], acc[i][3]};
        *(float4*)&cp[(ty * 4 + i) * D_ + tx * 4] = o;
    }
    if (tx == 0) {
        float* sp = ctxs + (size_t)chunk * (B_ * H_ * D_) + bh * D_;
        #pragma unroll
        for (int i = 0; i < 4; i++)
            sp[ty * 4 + i] = accs[i];
    }
}

__global__ __launch_bounds__(256) void ctx_reduce_kernel(
    const float* __restrict__ ctxp, const float* __restrict__ ctxs,
    float* __restrict__ ctx)
{
    int idx = blockIdx.x * 256 + threadIdx.x;
    const int total = B_ * H_ * D_ * D_;
    if (idx >= total) return;
    int bh = idx >> 12;
    int d  = (idx >> 6) & 63;
    float s = 0.f, se = 0.f;
    #pragma unroll
    for (int c = 0; c < NCHUNK; c++) {
        s  += ctxp[(size_t)c * total + idx];
        se += ctxs[(size_t)c * (B_ * H_ * D_) + bh * D_ + d];
    }
    ctx[idx] = s / se;
}

// ---------------------------------------------------------------------------
// M2t[b][c, h*64+d] = sum_e ctx[b,h,d,e] * wprojT[c, h*64+e]   (fp16 out)
// ---------------------------------------------------------------------------
__global__ __launch_bounds__(256) void m2_kernel(
    const float* __restrict__ ctx, const __half* __restrict__ wprojT,
    __half* __restrict__ m2t)
{
    int b = blockIdx.z, h = blockIdx.y, cc = blockIdx.x;
    __shared__ float cs[64 * 64];

    const float* cp = ctx + (size_t)(b * H_ + h) * D_ * D_;
    for (int i = threadIdx.x * 4; i < 4096; i += 1024)
        *(float4*)&cs[i] = *(const float4*)&cp[i];
    __syncthreads();

    int c = cc * 128 + (threadIdx.x >> 1);
    int d0 = (threadIdx.x & 1) * 32;

    float w[64];
    const __half2* wp = (const __half2*)(wprojT + (size_t)c * C_ + h * 64);
    #pragma unroll
    for (int e = 0; e < 32; e++) {
        float2 f = __half22float2(wp[e]);
        w[2*e] = f.x; w[2*e+1] = f.y;
    }

    float acc[32];
    #pragma unroll
    for (int i = 0; i < 32; i++) {
        const float4* rowp = (const float4*)(cs + (d0 + i) * 64);
        float a = 0.f;
        #pragma unroll
        for (int e4 = 0; e4 < 16; e4++) {
            float4 c4 = rowp[e4];
            a = fmaf(c4.x, w[4*e4], a);
            a = fmaf(c4.y, w[4*e4+1], a);
            a = fmaf(c4.z, w[4*e4+2], a);
            a = fmaf(c4.w, w[4*e4+3], a);
        }
        acc[i] = a;
    }

    uint32_t pk[16];
    #pragma unroll
    for (int j = 0; j < 16; j++) {
        __half2 hh = __floats2half2_rn(acc[2*j], acc[2*j+1]);
        pk[j] = *(uint32_t*)&hh;
    }
    __half* op = m2t + (size_t)b * C_ * C_ + (size_t)c * C_ + h * 64 + d0;
    #pragma unroll
    for (int j = 0; j < 4; j++) {
        uint4 o = {pk[4*j], pk[4*j+1], pk[4*j+2], pk[4*j+3]};
        *(uint4*)(op + j * 8) = o;
    }
}

// ---------------------------------------------------------------------------
extern "C" void kernel_launch(void* const* d_in, const int* in_sizes, int n_in,
                              void* d_out, int out_size)
{
    (void)in_sizes; (void)n_in; (void)out_size;
    const float* x     = (const float*)d_in[0];
    const float* Wqkv  = (const float*)d_in[1];
    const float* bqkv  = (const float*)d_in[2];
    const float* Wproj = (const float*)d_in[3];
    const float* bproj = (const float*)d_in[4];
    float* out = (float*)d_out;

    float *qkv, *ctx, *ctxp, *ctxs;
    __half *abuf, *qsm, *wqkvT, *wprojT, *m2t;
    cudaGetSymbolAddress((void**)&qkv,    g_qkv);
    cudaGetSymbolAddress((void**)&ctx,    g_ctx);
    cudaGetSymbolAddress((void**)&ctxp,   g_ctxp);
    cudaGetSymbolAddress((void**)&ctxs,   g_ctxs);
    cudaGetSymbolAddress((void**)&abuf,   g_abuf);
    cudaGetSymbolAddress((void**)&qsm,    g_qsm);
    cudaGetSymbolAddress((void**)&wqkvT,  g_wqkvT);
    cudaGetSymbolAddress((void**)&wprojT, g_wprojT);
    cudaGetSymbolAddress((void**)&m2t,    g_m2t);

    cudaFuncSetAttribute(gemm_mma_fp16<0>,
                         cudaFuncAttributeMaxDynamicSharedMemorySize, GEMM_SMEM);
    cudaFuncSetAttribute(gemm_mma_fp16<1>,
                         cudaFuncAttributeMaxDynamicSharedMemorySize, GEMM_SMEM);

    // 0) x -> fp16; weights -> [N,K] fp16
    round_x_kernel<<<M_TOT * C_ / 1024, 256>>>(x, abuf);
    transpose_kernel<<<dim3(QKV_N / 32, C_ / 32), dim3(32, 8)>>>(Wqkv, wqkvT, C_, QKV_N);
    transpose_kernel<<<dim3(C_ / 32, C_ / 32), dim3(32, 8)>>>(Wproj, wprojT, C_, C_);

    // 1) qkv GEMM, fused epilogue: q -> per-head softmax -> fp16 g_qsm;
    //    k -> exp(k+bias) fp32 in qkv; v -> plain fp32 in qkv.
    gemm_mma_fp16<1><<<dim3(QKV_N / 128, M_TOT / 128, 1), 128, GEMM_SMEM>>>(
        abuf, wqkvT, bqkv, qkv, qsm, M_TOT, QKV_N, C_, 0, 0, 0);

    // 2) context = softmax_N(k)^T v  (k region already exp'd; colsum-normalized)
    ctx_partial_kernel<<<dim3(B_ * H_, NCHUNK), 256>>>(qkv, ctxp, ctxs);
    ctx_reduce_kernel<<<(B_ * H_ * D_ * D_ + 255) / 256, 256>>>(ctxp, ctxs, ctx);

    // 3) M2t[b] = (ctx @ Wproj_head)^T fp16
    m2_kernel<<<dim3(8, H_, B_), 256>>>(ctx, wprojT, m2t);

    // 4) out[b] = q_sm[b] @ M2t[b]^T + bproj   (batched fp16 MMA GEMM)
    gemm_mma_fp16<0><<<dim3(C_ / 128, N_ / 128, B_), 128, GEMM_SMEM>>>(
        qsm, m2t, bproj, out, nullptr, N_, C_, C_,
        (size_t)N_ * C_, (size_t)C_ * C_, (size_t)N_ * C_);
}